// round 13
// baseline (speedup 1.0000x reference)
#include <cuda_runtime.h>
#include <cuda_bf16.h>

// Problem shapes (fixed by the dataset)
constexpr int Bsz = 4096;   // batch rows
constexpr int Lh  = 128;    // sequence length
constexpr int Dd  = 64;     // feature dim
constexpr int NC  = 129;    // possible count values 0..128
constexpr int TAIL = 32;    // positions with numerically relevant weight
                            // (e^{i-128} < 1.3e-14 relative for i < 96)

// LUT: f(c)[d] = sum_e relu(c*W1[e]+b1[e]) * W2[e][d]
__device__ float g_lut[NC * Dd];

__global__ void lut_kernel(const float* __restrict__ W1,
                           const float* __restrict__ b1,
                           const float* __restrict__ W2) {
    const int c = blockIdx.x;   // count value 0..128
    const int d = threadIdx.x;  // output dim 0..63
    __shared__ float h[Dd];
    h[d] = fmaxf(fmaf((float)c, W1[d], b1[d]), 0.0f);
    __syncthreads();
    float acc = 0.0f;
#pragma unroll
    for (int e = 0; e < Dd; e++)
        acc = fmaf(h[e], W2[e * Dd + d], acc);
    g_lut[c * Dd + d] = acc;
}

// One block per batch row, 256 threads:
//   thread t owns (side = t>>7, position i = t&127); side 0 = src, 1 = dst.
// No histogram: all 256 ids go to a flat shared table; only the 64 tail
// threads (warps 3 and 7) compute counts by scanning the table with
// broadcast LDS.128 (conflict-free), then fold exp-weights into the
// weighted count-histogram hw. First toucher of hw[c] registers c.
// Phase 3: out[side][b][d] = (sum_nz hw[c]*lut[c][d]) * (e-1) + 2*b2[d].
__global__ __launch_bounds__(256, 8) void pool_kernel(
    const int* __restrict__ src_ids, const int* __restrict__ dst_ids,
    const float* __restrict__ b2, float* __restrict__ out)
{
    __shared__ alignas(16) int s_ids[2 * Lh];   // [0:128)=src, [128:256)=dst
    __shared__ float s_hw[2][NC];               // weighted count histogram
    __shared__ int   s_nz[2][2 * TAIL];         // distinct counts touched
    __shared__ int   s_nnz[2];

    const int b    = blockIdx.x;
    const int t    = threadIdx.x;
    const int side = t >> 7;
    const int i    = t & 127;

    // each thread owns one (side, position) id; publish to shared table
    const int* ids = side ? dst_ids : src_ids;
    const int  id  = ids[b * Lh + i];
    s_ids[t] = id;

    // clear hw / nnz (no histogram clear anymore)
    if (t < 2 * NC) (&s_hw[0][0])[t] = 0.0f;
    if (t < 2)      { s_nnz[t] = 0; (&s_hw[0][0])[256 + t] = 0.0f; }
    __syncthreads();

    // ---- tail threads: direct count scan + weighted count histogram ----
    if (i >= Lh - TAIL) {                       // warps 3 and 7 exactly
        int c1 = 0, c2 = 0;                     // count in src list / dst list
        if (id != 0) {                          // padding forces counts to 0
            const int4* tab = reinterpret_cast<const int4*>(s_ids);
#pragma unroll 4
            for (int k = 0; k < 32; k++) {      // src half: 128 ids
                int4 v = tab[k];                // broadcast within warp
                c1 += (v.x == id) + (v.y == id) + (v.z == id) + (v.w == id);
            }
#pragma unroll 4
            for (int k = 32; k < 64; k++) {     // dst half: 128 ids
                int4 v = tab[k];
                c2 += (v.x == id) + (v.y == id) + (v.z == id) + (v.w == id);
            }
        }
        const float w = __expf((float)(i - Lh));
        float o1 = atomicAdd(&s_hw[side][c1], w);
        if (o1 == 0.0f) { int p = atomicAdd(&s_nnz[side], 1); s_nz[side][p] = c1; }
        float o2 = atomicAdd(&s_hw[side][c2], w);
        if (o2 == 0.0f) { int p = atomicAdd(&s_nnz[side], 1); s_nz[side][p] = c2; }
    }
    __syncthreads();

    // ---- sparse LUT contraction + epilogue ----
    if (t < 2 * Dd) {
        const int sd  = t >> 6;
        const int d   = t & (Dd - 1);
        const int nnz = s_nnz[sd];
        float acc = 0.0f;
        for (int m = 0; m < nnz; m++) {
            int c = s_nz[sd][m];                // broadcast LDS (same per side)
            acc = fmaf(s_hw[sd][c], g_lut[c * Dd + d], acc);
        }
        // 1 / w.sum() = (e-1)/(1 - e^-128) ~= e - 1
        out[sd * (Bsz * Dd) + b * Dd + d] =
            acc * 1.7182818284590452f + 2.0f * b2[d];
    }
}

extern "C" void kernel_launch(void* const* d_in, const int* in_sizes, int n_in,
                              void* d_out, int out_size) {
    const int*   src = (const int*)d_in[0];
    const int*   dst = (const int*)d_in[1];
    const float* W1  = (const float*)d_in[2];
    const float* b1  = (const float*)d_in[3];
    const float* W2  = (const float*)d_in[4];
    const float* b2  = (const float*)d_in[5];
    float* out = (float*)d_out;

    lut_kernel<<<NC, Dd>>>(W1, b1, W2);
    pool_kernel<<<Bsz, 256>>>(src, dst, b2, out);
}

// round 14
// speedup vs baseline: 1.3756x; 1.3756x over previous
#include <cuda_runtime.h>
#include <cuda_bf16.h>

// Problem shapes (fixed by the dataset)
constexpr int Bsz = 4096;   // batch rows
constexpr int Lh  = 128;    // sequence length
constexpr int Dd  = 64;     // feature dim
constexpr int NC  = 129;    // possible count values 0..128
constexpr int RPB = 4;      // batch rows per block  -> grid 1024 = single wave
constexpr int HST = 1024;   // u16 histogram stride per (row,list) (>=1000)

// LUT: f(c)[d] = sum_e relu(c*W1[e]+b1[e]) * W2[e][d]
__device__ float g_lut[NC * Dd];

__global__ void lut_kernel(const float* __restrict__ W1,
                           const float* __restrict__ b1,
                           const float* __restrict__ W2) {
    const int c = blockIdx.x;   // count value 0..128
    const int d = threadIdx.x;  // output dim 0..63
    __shared__ float h[Dd];
    h[d] = fmaxf(fmaf((float)c, W1[d], b1[d]), 0.0f);
    __syncthreads();
    float acc = 0.0f;
#pragma unroll
    for (int e = 0; e < Dd; e++)
        acc = fmaf(h[e], W2[e * Dd + d], acc);
    g_lut[c * Dd + d] = acc;
}

// One block = 4 batch rows, 256 threads. Thread t owns (side=t>>7, pos=t&127)
// in ALL 4 rows (4 independent LDGs -> MLP=4).
// Phase 1: packed-u16 id histograms (counts<=128, no cross-half carry).
// Phase 2: tail 32 positions/side (weights e^{i-128}<1.3e-14 for i<96 are
//          numerically irrelevant in f32) fold exp-weights into per-row-side
//          weighted count-histograms; first toucher registers count in nz.
// Phase 3: out[side][b][d] = (sum_nz hw[c]*lut[c][d]) * (e-1) + 2*b2[d].
__global__ __launch_bounds__(256, 8) void pool_kernel(
    const int* __restrict__ src_ids, const int* __restrict__ dst_ids,
    const float* __restrict__ b2, float* __restrict__ out)
{
    // [row][list] u16 histograms, packed two per u32 word
    __shared__ alignas(16) unsigned int s_hist[RPB * 2 * HST / 2]; // 16 KB
    __shared__ float s_hw[RPB * 2][NC + 3];    // weighted count histograms
    __shared__ int   s_nz[RPB * 2][64];        // distinct counts touched
    __shared__ int   s_nnz[RPB * 2];

    const int b0   = blockIdx.x * RPB;
    const int t    = threadIdx.x;
    const int side = t >> 7;
    const int i    = t & 127;

    // ---- load 4 ids up front (independent -> overlapped DRAM latency) ----
    const int* ids = side ? dst_ids : src_ids;
    int id[RPB];
#pragma unroll
    for (int r = 0; r < RPB; r++)
        id[r] = ids[(b0 + r) * Lh + i];

    // ---- clear shared state (vectorized) ----
    int4* h4 = reinterpret_cast<int4*>(s_hist);
#pragma unroll
    for (int k = t; k < (int)(sizeof(s_hist) / 16); k += 256)
        h4[k] = make_int4(0, 0, 0, 0);
    float* hwf = &s_hw[0][0];
#pragma unroll
    for (int k = t; k < RPB * 2 * (NC + 3); k += 256) hwf[k] = 0.0f;
    if (t < RPB * 2) s_nnz[t] = 0;
    __syncthreads();

    // ---- phase 1: histograms (u16 packed; increments never carry) ----
#pragma unroll
    for (int r = 0; r < RPB; r++) {
        int base = (r * 2 + side) * (HST / 2);
        atomicAdd(&s_hist[base + (id[r] >> 1)], 1u << ((id[r] & 1) * 16));
    }
    __syncthreads();

    // ---- phase 2: tail -> weighted count histograms ----
    if (i >= Lh - 32) {                         // warps 3 and 7
        const float w = __expf((float)(i - Lh));
#pragma unroll
        for (int r = 0; r < RPB; r++) {
            int c1 = 0, c2 = 0;
            if (id[r] != 0) {                   // padding forces counts to 0
                int wi = id[r] >> 1, sh = (id[r] & 1) * 16;
                c1 = (s_hist[(r * 2 + 0) * (HST / 2) + wi] >> sh) & 0xffff;
                c2 = (s_hist[(r * 2 + 1) * (HST / 2) + wi] >> sh) & 0xffff;
            }
            const int g = r * 2 + side;
            float o1 = atomicAdd(&s_hw[g][c1], w);
            if (o1 == 0.0f) { int p = atomicAdd(&s_nnz[g], 1); s_nz[g][p] = c1; }
            float o2 = atomicAdd(&s_hw[g][c2], w);
            if (o2 == 0.0f) { int p = atomicAdd(&s_nnz[g], 1); s_nz[g][p] = c2; }
        }
    }
    __syncthreads();

    // ---- phase 3: sparse LUT contraction + epilogue (512 outputs) ----
    {
        const int d  = t & (Dd - 1);
        const float bb = 2.0f * b2[d];
#pragma unroll
        for (int half = 0; half < 2; half++) {
            const int g   = (t >> 6) + half * 4;   // row-side group 0..7
            const int r   = g >> 1;
            const int sd  = g & 1;
            const int nnz = s_nnz[g];
            float acc = 0.0f;
            for (int m = 0; m < nnz; m++) {
                int c = s_nz[g][m];             // broadcast LDS within warp
                acc = fmaf(s_hw[g][c], g_lut[c * Dd + d], acc);
            }
            // 1 / w.sum() = (e-1)/(1 - e^-128) ~= e - 1
            out[sd * (Bsz * Dd) + (b0 + r) * Dd + d] =
                acc * 1.7182818284590452f + bb;
        }
    }
}

extern "C" void kernel_launch(void* const* d_in, const int* in_sizes, int n_in,
                              void* d_out, int out_size) {
    const int*   src = (const int*)d_in[0];
    const int*   dst = (const int*)d_in[1];
    const float* W1  = (const float*)d_in[2];
    const float* b1  = (const float*)d_in[3];
    const float* W2  = (const float*)d_in[4];
    const float* b2  = (const float*)d_in[5];
    float* out = (float*)d_out;

    lut_kernel<<<NC, Dd>>>(W1, b1, W2);
    pool_kernel<<<Bsz / RPB, 256>>>(src, dst, b2, out);
}

// round 15
// speedup vs baseline: 1.4184x; 1.0311x over previous
#include <cuda_runtime.h>
#include <cuda_bf16.h>

// Problem shapes (fixed by the dataset)
constexpr int Bsz = 4096;   // batch rows
constexpr int Lh  = 128;    // sequence length
constexpr int Dd  = 64;     // feature dim
constexpr int NC  = 129;    // possible count values 0..128
constexpr int RPB = 4;      // batch rows per block -> grid 1024 = single wave
constexpr int TAIL = 32;    // positions with numerically relevant weight
                            // (e^{i-128} < 1.3e-14 relative for i < 96)

// LUT: f(c)[d] = sum_e relu(c*W1[e]+b1[e]) * W2[e][d]
__device__ float g_lut[NC * Dd];

__global__ void lut_kernel(const float* __restrict__ W1,
                           const float* __restrict__ b1,
                           const float* __restrict__ W2) {
    const int c = blockIdx.x;   // count value 0..128
    const int d = threadIdx.x;  // output dim 0..63
    __shared__ float h[Dd];
    h[d] = fmaxf(fmaf((float)c, W1[d], b1[d]), 0.0f);
    __syncthreads();
    float acc = 0.0f;
#pragma unroll
    for (int e = 0; e < Dd; e++)
        acc = fmaf(h[e], W2[e * Dd + d], acc);
    g_lut[c * Dd + d] = acc;
}

// One block = 4 batch rows, 256 threads. Thread t owns (side=t>>7, pos=t&127)
// in all 4 rows. NO histogram, NO mass atomics:
// Phase 1: publish all ids to shared table s_ids[row][side][pos].
// Phase 2: warp w of 8 -> (row = w>>1, query side = w&1); lane j owns tail
//          query position 96+j; scans the row's full 256-id table with
//          broadcast LDS.128 to get counts vs src list (c1) and dst list
//          (c2); folds exp-weight into the weighted count-histogram hw.
//          First toucher of hw[g][c] registers c in the nz list.
// Phase 3: out[side][b][d] = (sum_nz hw[c]*lut[c][d]) * (e-1) + 2*b2[d].
__global__ __launch_bounds__(256, 8) void pool_kernel(
    const int* __restrict__ src_ids, const int* __restrict__ dst_ids,
    const float* __restrict__ b2, float* __restrict__ out)
{
    __shared__ alignas(16) int s_ids[RPB * 2 * Lh];  // 4 KB id tables
    __shared__ float s_hw[RPB * 2][NC + 3];          // weighted count hists
    __shared__ int   s_nz[RPB * 2][4 * TAIL];        // distinct counts touched
    __shared__ int   s_nnz[RPB * 2];

    const int b0   = blockIdx.x * RPB;
    const int t    = threadIdx.x;
    const int side = t >> 7;
    const int i    = t & 127;

    // ---- phase 1: load + publish ids (4 independent LDGs, MLP=4) ----
    const int* ids = side ? dst_ids : src_ids;
#pragma unroll
    for (int r = 0; r < RPB; r++)
        s_ids[(r * 2 + side) * Lh + i] = ids[(b0 + r) * Lh + i];

    // clear hw / nnz
    float* hwf = &s_hw[0][0];
#pragma unroll
    for (int k = t; k < RPB * 2 * (NC + 3); k += 256) hwf[k] = 0.0f;
    if (t < RPB * 2) s_nnz[t] = 0;
    __syncthreads();

    // ---- phase 2: balanced tail-query scan -> weighted count histograms --
    {
        const int w    = t >> 5;          // warp 0..7
        const int lane = t & 31;
        const int r    = w >> 1;          // row this warp serves
        const int qh   = w & 1;           // query side (0=src,1=dst)
        const int q    = s_ids[(r * 2 + qh) * Lh + (Lh - TAIL) + lane];

        int c1 = 0, c2 = 0;
        if (q != 0) {                     // padding forces counts to 0
            const int4* stab = reinterpret_cast<const int4*>(&s_ids[(r * 2 + 0) * Lh]);
            const int4* dtab = reinterpret_cast<const int4*>(&s_ids[(r * 2 + 1) * Lh]);
#pragma unroll 8
            for (int k = 0; k < Lh / 4; k++) {
                int4 v = stab[k];         // broadcast LDS.128 (conflict-free)
                int4 u = dtab[k];
                c1 += (v.x == q) + (v.y == q) + (v.z == q) + (v.w == q);
                c2 += (u.x == q) + (u.y == q) + (u.z == q) + (u.w == q);
            }
        }
        const float wgt = __expf((float)(lane - TAIL));  // e^{i-L}, i=96+lane
        const int g = r * 2 + qh;
        float o1 = atomicAdd(&s_hw[g][c1], wgt);
        if (o1 == 0.0f) { int p = atomicAdd(&s_nnz[g], 1); s_nz[g][p] = c1; }
        float o2 = atomicAdd(&s_hw[g][c2], wgt);
        if (o2 == 0.0f) { int p = atomicAdd(&s_nnz[g], 1); s_nz[g][p] = c2; }
    }
    __syncthreads();

    // ---- phase 3: sparse LUT contraction + epilogue (512 outputs) ----
    {
        const int d  = t & (Dd - 1);
        const float bb = 2.0f * b2[d];
#pragma unroll
        for (int half = 0; half < 2; half++) {
            const int g   = (t >> 6) + half * 4;   // row-side group 0..7
            const int r   = g >> 1;
            const int sd  = g & 1;
            const int nnz = s_nnz[g];
            float acc = 0.0f;
            for (int m = 0; m < nnz; m++) {
                int c = s_nz[g][m];                // broadcast LDS
                acc = fmaf(s_hw[g][c], g_lut[c * Dd + d], acc);
            }
            // 1 / w.sum() = (e-1)/(1 - e^-128) ~= e - 1
            out[sd * (Bsz * Dd) + (b0 + r) * Dd + d] =
                acc * 1.7182818284590452f + bb;
        }
    }
}

extern "C" void kernel_launch(void* const* d_in, const int* in_sizes, int n_in,
                              void* d_out, int out_size) {
    const int*   src = (const int*)d_in[0];
    const int*   dst = (const int*)d_in[1];
    const float* W1  = (const float*)d_in[2];
    const float* b1  = (const float*)d_in[3];
    const float* W2  = (const float*)d_in[4];
    const float* b2  = (const float*)d_in[5];
    float* out = (float*)d_out;

    lut_kernel<<<NC, Dd>>>(W1, b1, W2);
    pool_kernel<<<Bsz / RPB, 256>>>(src, dst, b2, out);
}

// round 16
// speedup vs baseline: 2.6982x; 1.9024x over previous
#include <cuda_runtime.h>
#include <cuda_fp16.h>
#include <cuda_bf16.h>

// Problem shapes (fixed by the dataset)
constexpr int Bsz = 4096;   // batch rows
constexpr int Lh  = 128;    // sequence length
constexpr int Dd  = 64;     // feature dim
constexpr int NC  = 129;    // possible count values 0..128
constexpr int RPB = 4;      // batch rows per block -> grid 1024 = single wave
constexpr int TAIL = 16;    // positions kept: dropped mass e^-16 ~ 1.1e-7 rel

// LUT: f(c)[d] = sum_e relu(c*W1[e]+b1[e]) * W2[e][d]
__device__ float g_lut[NC * Dd];

__global__ void lut_kernel(const float* __restrict__ W1,
                           const float* __restrict__ b1,
                           const float* __restrict__ W2) {
    const int c = blockIdx.x;   // count value 0..128
    const int d = threadIdx.x;  // output dim 0..63
    __shared__ float h[Dd];
    h[d] = fmaxf(fmaf((float)c, W1[d], b1[d]), 0.0f);
    __syncthreads();
    float acc = 0.0f;
#pragma unroll
    for (int e = 0; e < Dd; e++)
        acc = fmaf(h[e], W2[e * Dd + d], acc);
    g_lut[c * Dd + d] = acc;
}

// One block = 4 batch rows, 256 threads.
// Phase 1: ids -> shared as fp16 (ids<1000 exact in fp16).
// Phase 2: warp w of 8 -> (row=w>>1, query side=w&1). Lane j<16: count of
//          query j in SRC table; lane j+16: same query in DST table — both
//          channels feed the same hw (reference sums channels). Each lane
//          scans 128 fp16 ids with __heq2/__hadd2: 1 instr/element on the
//          FMA pipe. Exp-weight folded into weighted count-histogram hw;
//          first toucher of hw[g][c] registers c in the nz list.
// Phase 3: out[side][b][d] = (sum_nz hw[c]*lut[c][d]) * (e-1) + 2*b2[d].
__global__ __launch_bounds__(256, 8) void pool_kernel(
    const int* __restrict__ src_ids, const int* __restrict__ dst_ids,
    const float* __restrict__ b2, float* __restrict__ out)
{
    __shared__ alignas(16) __half s_idsh[RPB * 2 * Lh];  // 2 KB fp16 tables
    __shared__ float s_hw[RPB * 2][NC + 3];              // weighted count hist
    __shared__ int   s_nz[RPB * 2][4 * TAIL];            // counts touched
    __shared__ int   s_nnz[RPB * 2];

    const int b0   = blockIdx.x * RPB;
    const int t    = threadIdx.x;
    const int side = t >> 7;
    const int i    = t & 127;

    // ---- phase 1: load ids (4 independent LDGs), publish as fp16 ----
    const int* ids = side ? dst_ids : src_ids;
#pragma unroll
    for (int r = 0; r < RPB; r++)
        s_idsh[(r * 2 + side) * Lh + i] = __int2half_rn(ids[(b0 + r) * Lh + i]);

    // clear hw / nnz
    float* hwf = &s_hw[0][0];
#pragma unroll
    for (int k = t; k < RPB * 2 * (NC + 3); k += 256) hwf[k] = 0.0f;
    if (t < RPB * 2) s_nnz[t] = 0;
    __syncthreads();

    // ---- phase 2: fp16 SIMD count scan -> weighted count histograms ----
    {
        const int w    = t >> 5;          // warp 0..7
        const int lane = t & 31;
        const int r    = w >> 1;          // row this warp serves
        const int qh   = w & 1;           // query side (0=src,1=dst)
        const int tb   = lane >> 4;       // table this lane scans
        const int j    = lane & 15;       // tail query index 0..15

        const __half q = s_idsh[(r * 2 + qh) * Lh + (Lh - TAIL) + j];
        const __half2 qq = __half2half2(q);

        const uint4* tab =
            reinterpret_cast<const uint4*>(&s_idsh[(r * 2 + tb) * Lh]);
        __half2 a0 = __float2half2_rn(0.f), a1 = a0, a2 = a0, a3 = a0;
#pragma unroll
        for (int k = 0; k < Lh / 8; k++) {          // 16 x LDS.128 broadcast
            uint4 v = tab[k];
            a0 = __hadd2(a0, __heq2(*reinterpret_cast<__half2*>(&v.x), qq));
            a1 = __hadd2(a1, __heq2(*reinterpret_cast<__half2*>(&v.y), qq));
            a2 = __hadd2(a2, __heq2(*reinterpret_cast<__half2*>(&v.z), qq));
            a3 = __hadd2(a3, __heq2(*reinterpret_cast<__half2*>(&v.w), qq));
        }
        const __half2 acc = __hadd2(__hadd2(a0, a1), __hadd2(a2, a3));
        int c = (int)(__low2float(acc) + __high2float(acc));
        if (__half2float(q) == 0.0f) c = 0;         // padding forces count 0

        const float wgt = __expf((float)(j - TAIL)); // e^{pos-L}, pos=112+j
        const int g = r * 2 + qh;
        float o = atomicAdd(&s_hw[g][c], wgt);
        if (o == 0.0f) { int p = atomicAdd(&s_nnz[g], 1); s_nz[g][p] = c; }
    }
    __syncthreads();

    // ---- phase 3: sparse LUT contraction + epilogue (512 outputs) ----
    {
        const int d  = t & (Dd - 1);
        const float bb = 2.0f * b2[d];
#pragma unroll
        for (int half = 0; half < 2; half++) {
            const int g   = (t >> 6) + half * 4;   // row-side group 0..7
            const int r   = g >> 1;
            const int sd  = g & 1;
            const int nnz = s_nnz[g];
            float acc = 0.0f;
            for (int m = 0; m < nnz; m++) {
                int c = s_nz[g][m];                // broadcast LDS
                acc = fmaf(s_hw[g][c], g_lut[c * Dd + d], acc);
            }
            // 1 / w.sum() = (e-1)/(1 - e^-128) ~= e - 1
            out[sd * (Bsz * Dd) + (b0 + r) * Dd + d] =
                acc * 1.7182818284590452f + bb;
        }
    }
}

extern "C" void kernel_launch(void* const* d_in, const int* in_sizes, int n_in,
                              void* d_out, int out_size) {
    const int*   src = (const int*)d_in[0];
    const int*   dst = (const int*)d_in[1];
    const float* W1  = (const float*)d_in[2];
    const float* b1  = (const float*)d_in[3];
    const float* W2  = (const float*)d_in[4];
    const float* b2  = (const float*)d_in[5];
    float* out = (float*)d_out;

    lut_kernel<<<NC, Dd>>>(W1, b1, W2);
    pool_kernel<<<Bsz / RPB, 256>>>(src, dst, b2, out);
}